// round 12
// baseline (speedup 1.0000x reference)
#include <cuda_runtime.h>
#include <cstdint>

#define Vdim 2048
#define Sdim 1024
#define Edim 64

#define NCONS  256                 // consumer threads (8 warps)
#define NPROD  128                 // producer threads (4 warps)
#define NTHR   (NCONS + NPROD)     // 384
#define KCH    32                  // v per chunk
#define NCHUNK (Vdim / KCH)        // 64
#define S_TILE 128
#define NSTG   5                   // input-only stages (emb no longer staged)
#define NTILES ((Sdim / S_TILE) * 128)     // 1024
#define NCTA   304                 // 2 per SM x 152 SMs (GB300)

// smem layout (floats): sIn rows padded 128->136
#define IN_ROW    136
#define IN_STAGE  (KCH * IN_ROW)           // 17408 B
#define STAGE_END (NSTG * IN_STAGE * 4)    // 87040
#define FULL_OFF   STAGE_END               // 5 x 8B
#define EMPTY_OFF  (STAGE_END + 48)        // 5 x 8B
#define TFULL_OFF  (STAGE_END + 96)        // 4 x 8B
#define TEMPTY_OFF (STAGE_END + 128)       // 4 x 8B
#define TILEID_OFF (STAGE_END + 160)       // 4 x 4B
#define SMEM_BYTES (STAGE_END + 192)

// emb, tf32-RNA-rounded, pre-scaled by (1+2^-12) to cancel input-truncation bias
__device__ __align__(16) float g_embR[Vdim * Edim];
__device__ int g_ticket;

__global__ void round_emb(const float* __restrict__ emb) {
    int i = blockIdx.x * 256 + threadIdx.x;
    if (i == 0) g_ticket = 0;                 // reset scheduler every launch/replay
    if (i < Vdim * Edim) {
        float v = emb[i] * 1.000244140625f;
        uint32_t r;
        asm("cvt.rna.tf32.f32 %0, %1;" : "=r"(r) : "f"(v));
        g_embR[i] = __uint_as_float(r);
    }
}

__device__ __forceinline__ uint32_t smem_u32(const void* p) {
    uint32_t a;
    asm("{ .reg .u64 t; cvta.to.shared.u64 t, %1; cvt.u32.u64 %0, t; }" : "=r"(a) : "l"(p));
    return a;
}
__device__ __forceinline__ void cp16(uint32_t dst, const void* src) {
    asm volatile("cp.async.cg.shared.global [%0], [%1], 16;" :: "r"(dst), "l"(src) : "memory");
}
__device__ __forceinline__ void mma_tf32(float& c0, float& c1, float& c2, float& c3,
                                         uint32_t a0, uint32_t a1, uint32_t a2, uint32_t a3,
                                         uint32_t b0, uint32_t b1) {
    asm volatile(
        "mma.sync.aligned.m16n8k8.row.col.f32.tf32.tf32.f32 "
        "{%0,%1,%2,%3}, {%4,%5,%6,%7}, {%8,%9}, {%0,%1,%2,%3};"
        : "+f"(c0), "+f"(c1), "+f"(c2), "+f"(c3)
        : "r"(a0), "r"(a1), "r"(a2), "r"(a3), "r"(b0), "r"(b1));
}

#define MBAR_INIT(a, c) \
    asm volatile("mbarrier.init.shared.b64 [%0], %1;" :: "r"(a), "r"(c) : "memory")
#define MBAR_ARRIVE(a) \
    asm volatile("mbarrier.arrive.shared.b64 _, [%0];" :: "r"(a) : "memory")
#define CPASYNC_MBAR_ARRIVE(a) \
    asm volatile("cp.async.mbarrier.arrive.noinc.shared::cta.b64 [%0];" :: "r"(a) : "memory")
#define MBAR_WAIT(a, p) do {                                                      \
    uint32_t _done = 0;                                                           \
    while (!_done) {                                                              \
        asm volatile("{\n\t.reg .pred P;\n\t"                                     \
            "mbarrier.try_wait.parity.acquire.cta.shared::cta.b64 P, [%1], %2, 0x989680;\n\t" \
            "selp.b32 %0, 1, 0, P;\n\t}"                                          \
            : "=r"(_done) : "r"(a), "r"(p) : "memory");                           \
    } } while (0)

__global__ __launch_bounds__(NTHR, 2)
void embed_mma_kernel(const float* __restrict__ inp, float* __restrict__ out)
{
    extern __shared__ char smem[];
    float* sInF = (float*)smem;
    volatile int* tileIds = (volatile int*)(smem + TILEID_OFF);
    const uint32_t sb = smem_u32(smem);

    const int tid = threadIdx.x;

    if (tid == 0) {
#pragma unroll
        for (int s = 0; s < NSTG; ++s) {
            MBAR_INIT(sb + FULL_OFF  + 8 * s, NPROD);   // 128 noinc completion-arrives
            MBAR_INIT(sb + EMPTY_OFF + 8 * s, 8);       // 8 consumer warp leaders
        }
#pragma unroll
        for (int s = 0; s < 4; ++s) {
            MBAR_INIT(sb + TFULL_OFF  + 8 * s, 1);      // producer leader
            MBAR_INIT(sb + TEMPTY_OFF + 8 * s, 8);      // 8 consumer warp leaders
        }
    }
    __syncthreads();

    if (tid >= NCONS) {
        // ================= PRODUCER (4 warps, input only) =================
        const int ptid = tid - NCONS;                   // 0..127
        int gc = 0, slot = 0, ph = 0;                   // chunk ring state (mod-5)
        for (int t = 0; ; ++t) {
            const int ts = t & 3;
            if (ptid == 0) {
                if (t >= 4) MBAR_WAIT(sb + TEMPTY_OFF + 8 * ts, ((t >> 2) - 1) & 1);
                int id = atomicAdd(&g_ticket, 1);
                if (id >= NTILES) id = -1;
                tileIds[ts] = id;
                MBAR_ARRIVE(sb + TFULL_OFF + 8 * ts);   // release: id visible to waiters
            }
            MBAR_WAIT(sb + TFULL_OFF + 8 * ts, (t >> 2) & 1);
            const int id = tileIds[ts];
            if (id < 0) break;
            const float* inB = inp + (size_t)(id >> 3) * Vdim * Sdim + (id & 7) * S_TILE;
            for (int c = 0; c < NCHUNK; ++c) {
                if (gc >= NSTG)
                    MBAR_WAIT(sb + EMPTY_OFF + 8 * slot, ph ^ 1);
                const int v0 = c * KCH;
                uint32_t inDst = sb + slot * (IN_STAGE * 4);
#pragma unroll
                for (int u = 0; u < 8; ++u) {           // input: 1024 float4 / 128 thr
                    int idx = ptid + u * NPROD;
                    int row = idx >> 5, col4 = idx & 31;
                    cp16(inDst + row * (IN_ROW * 4) + col4 * 16,
                         inB + (size_t)(v0 + row) * Sdim + col4 * 4);
                }
                CPASYNC_MBAR_ARRIVE(sb + FULL_OFF + 8 * slot);
                ++gc; if (++slot == NSTG) { slot = 0; ph ^= 1; }
            }
        }
        return;
    }

    // ================= CONSUMER (8 warps, 32s x 32e warp tile) =================
    const int w    = tid >> 5;
    const int lane = tid & 31;
    const int sbase = (w & 3) * 32;
    const int ebase = (w >> 2) * 32;
    const int gid = lane >> 2, tig = lane & 3;

    // B-fragment base in global (L1/L2-cached, same 8KB tile shared by all warps)
    const float* gBbase = g_embR + ebase + gid;

    int slot = 0, ph = 0;
    for (int t = 0; ; ++t) {
        const int ts = t & 3;
        MBAR_WAIT(sb + TFULL_OFF + 8 * ts, (t >> 2) & 1);
        const int id = tileIds[ts];
        __syncwarp();
        if (lane == 0) MBAR_ARRIVE(sb + TEMPTY_OFF + 8 * ts);
        if (id < 0) break;

        float acc[2][4][4];
#pragma unroll
        for (int i = 0; i < 2; ++i)
#pragma unroll
            for (int n = 0; n < 4; ++n)
#pragma unroll
                for (int cc = 0; cc < 4; ++cc) acc[i][n][cc] = 0.0f;

        for (int c = 0; c < NCHUNK; ++c) {
            MBAR_WAIT(sb + FULL_OFF + 8 * slot, ph);

            const float* aP = sInF + slot * IN_STAGE + tig * IN_ROW + sbase + gid;
            const float* gB = gBbase + (size_t)(c * KCH + tig) * Edim;
#pragma unroll
            for (int k8 = 0; k8 < 4; ++k8) {
                const int ka = k8 * 8 * IN_ROW;
                const int kb = k8 * 8 * Edim;           // 8 v-rows per k-step
                uint32_t bf[4][2];
#pragma unroll
                for (int n = 0; n < 4; ++n) {
                    bf[n][0] = __float_as_uint(__ldg(gB + kb + 8 * n));
                    bf[n][1] = __float_as_uint(__ldg(gB + kb + 4 * Edim + 8 * n));
                }
#pragma unroll
                for (int i = 0; i < 2; ++i) {
                    uint32_t a0 = __float_as_uint(aP[ka + 16 * i]);
                    uint32_t a1 = __float_as_uint(aP[ka + 16 * i + 8]);
                    uint32_t a2 = __float_as_uint(aP[ka + 16 * i + 4 * IN_ROW]);
                    uint32_t a3 = __float_as_uint(aP[ka + 16 * i + 4 * IN_ROW + 8]);
#pragma unroll
                    for (int n = 0; n < 4; ++n)
                        mma_tf32(acc[i][n][0], acc[i][n][1], acc[i][n][2], acc[i][n][3],
                                 a0, a1, a2, a3, bf[n][0], bf[n][1]);
                }
            }
            __syncwarp();
            if (lane == 0) MBAR_ARRIVE(sb + EMPTY_OFF + 8 * slot);
            if (++slot == NSTG) { slot = 0; ph ^= 1; }
        }

        // epilogue for this tile
        float* oB = out + ((size_t)(id >> 3) * Sdim + (id & 7) * S_TILE + sbase + gid) * Edim
                        + ebase + tig * 2;
#pragma unroll
        for (int i = 0; i < 2; ++i) {
#pragma unroll
            for (int n = 0; n < 4; ++n) {
                float2 lo = make_float2(acc[i][n][0], acc[i][n][1]);
                float2 hi = make_float2(acc[i][n][2], acc[i][n][3]);
                *(float2*)(oB + (size_t)(16 * i) * Edim + 8 * n)     = lo;
                *(float2*)(oB + (size_t)(16 * i + 8) * Edim + 8 * n) = hi;
            }
        }
    }
}

extern "C" void kernel_launch(void* const* d_in, const int* in_sizes, int n_in,
                              void* d_out, int out_size) {
    const float* inp = (const float*)d_in[0];   // [128, 2048, 1024] fp32
    const float* emb = (const float*)d_in[1];   // [2048, 64] fp32
    float* out = (float*)d_out;                 // [128, 1024, 64] fp32

    round_emb<<<(Vdim * Edim + 255) / 256, 256>>>(emb);

    cudaFuncSetAttribute(embed_mma_kernel,
                         cudaFuncAttributeMaxDynamicSharedMemorySize, SMEM_BYTES);
    embed_mma_kernel<<<NCTA, NTHR, SMEM_BYTES>>>(inp, out);
}

// round 13
// speedup vs baseline: 1.9113x; 1.9113x over previous
#include <cuda_runtime.h>
#include <cstdint>

#define Vdim 2048
#define Sdim 1024
#define Edim 64

#define NCONS  256                 // consumer threads (8 warps)
#define NPROD  128                 // producer threads (4 warps)
#define NTHR   (NCONS + NPROD)     // 384
#define KCH    32                  // v per chunk
#define NCHUNK (Vdim / KCH)        // 64
#define S_TILE 128
#define NSTG   4
#define NTILES ((Sdim / S_TILE) * 128)     // 1024
#define NCTA   304                 // 2 per SM x 152 SMs (GB300)

// smem layout: sIn rows padded 128->136 floats; emb fragment-packed, unpadded
#define IN_ROW    136
#define IN_STAGE  (KCH * IN_ROW)           // 17408 B per stage (floats*4)
#define EMB_STAGE_B 8192                   // 2048 floats, fragment-packed
#define EMB_OFF   (NSTG * IN_STAGE * 4)    // 69632
#define STAGE_END (EMB_OFF + NSTG * EMB_STAGE_B)     // 102400
#define FULL_OFF   STAGE_END               // 4 x 8B
#define EMPTY_OFF  (STAGE_END + 32)
#define TFULL_OFF  (STAGE_END + 64)
#define TEMPTY_OFF (STAGE_END + 96)
#define TILEID_OFF (STAGE_END + 128)       // 4 x 4B
#define SMEM_BYTES (STAGE_END + 160)

// Fragment-packed emb: p = ((bk*2 + eg)*32 + lane)*8 + (half*4 + n)
//   bk = global k8 index (v block of 8), eg = e-half (0/1), lane: tig=l&3, gid=l>>2
//   value = tf32_rna(emb[bk*8 + half*4 + tig][eg*32 + gid + 8n] * (1+2^-12))
__device__ __align__(16) float g_embP[Vdim * Edim];
__device__ int g_ticket;

__global__ void pack_emb(const float* __restrict__ emb) {
    int p = blockIdx.x * 256 + threadIdx.x;
    if (p == 0) g_ticket = 0;                 // reset scheduler every launch/replay
    if (p < Vdim * Edim) {
        int bk   = p >> 9;
        int rem  = p & 511;
        int eg   = rem >> 8;
        int l    = (rem >> 3) & 31;
        int j    = rem & 7;
        int tig  = l & 3, gid = l >> 2;
        int half = j >> 2, n = j & 3;
        int v = bk * 8 + half * 4 + tig;
        int e = eg * 32 + gid + 8 * n;
        float val = emb[v * Edim + e] * 1.000244140625f;  // cancel input-trunc bias
        uint32_t r;
        asm("cvt.rna.tf32.f32 %0, %1;" : "=r"(r) : "f"(val));
        g_embP[p] = __uint_as_float(r);
    }
}

__device__ __forceinline__ uint32_t smem_u32(const void* p) {
    uint32_t a;
    asm("{ .reg .u64 t; cvta.to.shared.u64 t, %1; cvt.u32.u64 %0, t; }" : "=r"(a) : "l"(p));
    return a;
}
__device__ __forceinline__ void cp16(uint32_t dst, const void* src) {
    asm volatile("cp.async.cg.shared.global [%0], [%1], 16;" :: "r"(dst), "l"(src) : "memory");
}
__device__ __forceinline__ void mma_tf32(float& c0, float& c1, float& c2, float& c3,
                                         uint32_t a0, uint32_t a1, uint32_t a2, uint32_t a3,
                                         uint32_t b0, uint32_t b1) {
    asm volatile(
        "mma.sync.aligned.m16n8k8.row.col.f32.tf32.tf32.f32 "
        "{%0,%1,%2,%3}, {%4,%5,%6,%7}, {%8,%9}, {%0,%1,%2,%3};"
        : "+f"(c0), "+f"(c1), "+f"(c2), "+f"(c3)
        : "r"(a0), "r"(a1), "r"(a2), "r"(a3), "r"(b0), "r"(b1));
}

#define MBAR_INIT(a, c) \
    asm volatile("mbarrier.init.shared.b64 [%0], %1;" :: "r"(a), "r"(c) : "memory")
#define MBAR_ARRIVE(a) \
    asm volatile("mbarrier.arrive.shared.b64 _, [%0];" :: "r"(a) : "memory")
#define CPASYNC_MBAR_ARRIVE(a) \
    asm volatile("cp.async.mbarrier.arrive.noinc.shared::cta.b64 [%0];" :: "r"(a) : "memory")
#define MBAR_WAIT(a, p) do {                                                      \
    uint32_t _done = 0;                                                           \
    while (!_done) {                                                              \
        asm volatile("{\n\t.reg .pred P;\n\t"                                     \
            "mbarrier.try_wait.parity.acquire.cta.shared::cta.b64 P, [%1], %2, 0x989680;\n\t" \
            "selp.b32 %0, 1, 0, P;\n\t}"                                          \
            : "=r"(_done) : "r"(a), "r"(p) : "memory");                           \
    } } while (0)

__global__ __launch_bounds__(NTHR, 2)
void embed_mma_kernel(const float* __restrict__ inp, float* __restrict__ out)
{
    extern __shared__ char smem[];
    float* sInF = (float*)smem;
    volatile int* tileIds = (volatile int*)(smem + TILEID_OFF);
    const uint32_t sb = smem_u32(smem);

    const int tid = threadIdx.x;

    if (tid == 0) {
#pragma unroll
        for (int s = 0; s < NSTG; ++s) {
            MBAR_INIT(sb + FULL_OFF   + 8 * s, NPROD);  // 128 noinc completion-arrives
            MBAR_INIT(sb + EMPTY_OFF  + 8 * s, 8);      // 8 consumer warp leaders
            MBAR_INIT(sb + TFULL_OFF  + 8 * s, 1);      // producer leader
            MBAR_INIT(sb + TEMPTY_OFF + 8 * s, 8);      // 8 consumer warp leaders
        }
    }
    __syncthreads();

    if (tid >= NCONS) {
        // ================= PRODUCER (4 warps) =================
        const int ptid = tid - NCONS;                   // 0..127
        int gc = 0;                                     // global chunk sequence
        for (int t = 0; ; ++t) {
            const int ts = t & 3;
            if (ptid == 0) {
                if (t >= 4) MBAR_WAIT(sb + TEMPTY_OFF + 8 * ts, ((t >> 2) - 1) & 1);
                int id = atomicAdd(&g_ticket, 1);
                if (id >= NTILES) id = -1;
                tileIds[ts] = id;
                MBAR_ARRIVE(sb + TFULL_OFF + 8 * ts);   // release: id visible to waiters
            }
            MBAR_WAIT(sb + TFULL_OFF + 8 * ts, (t >> 2) & 1);
            const int id = tileIds[ts];
            if (id < 0) break;
            const float* inB = inp + (size_t)(id >> 3) * Vdim * Sdim + (id & 7) * S_TILE;
            for (int c = 0; c < NCHUNK; ++c, ++gc) {
                const int slot = gc & 3;
                if (gc >= NSTG)
                    MBAR_WAIT(sb + EMPTY_OFF + 8 * slot, ((gc >> 2) - 1) & 1);
                const int v0 = c * KCH;
                uint32_t inDst  = sb + slot * (IN_STAGE * 4);
                uint32_t embDst = sb + EMB_OFF + slot * EMB_STAGE_B;
#pragma unroll
                for (int u = 0; u < 8; ++u) {           // input: 1024 float4 / 128 thr
                    int idx = ptid + u * NPROD;
                    int row = idx >> 5, col4 = idx & 31;
                    cp16(inDst + row * (IN_ROW * 4) + col4 * 16,
                         inB + (size_t)(v0 + row) * Sdim + col4 * 4);
                }
                // emb: 8192B contiguous (fragment-packed), 512 float4 / 128 thr
                const float* embSrc = g_embP + (size_t)c * 2048;
#pragma unroll
                for (int u = 0; u < 4; ++u) {
                    int idx = ptid + u * NPROD;
                    cp16(embDst + idx * 16, embSrc + idx * 4);
                }
                CPASYNC_MBAR_ARRIVE(sb + FULL_OFF + 8 * slot);
            }
        }
        return;
    }

    // ================= CONSUMER (8 warps, 32s x 32e warp tile) =================
    const int w    = tid >> 5;
    const int lane = tid & 31;
    const int sbase = (w & 3) * 32;
    const int eg    = w >> 2;            // e-half
    const int gid = lane >> 2, tig = lane & 3;

    int gc = 0;
    for (int t = 0; ; ++t) {
        const int ts = t & 3;
        MBAR_WAIT(sb + TFULL_OFF + 8 * ts, (t >> 2) & 1);
        const int id = tileIds[ts];
        __syncwarp();
        if (lane == 0) MBAR_ARRIVE(sb + TEMPTY_OFF + 8 * ts);
        if (id < 0) break;

        float acc[2][4][4];
#pragma unroll
        for (int i = 0; i < 2; ++i)
#pragma unroll
            for (int n = 0; n < 4; ++n)
#pragma unroll
                for (int cc = 0; cc < 4; ++cc) acc[i][n][cc] = 0.0f;

        for (int c = 0; c < NCHUNK; ++c, ++gc) {
            const int slot = gc & 3;
            MBAR_WAIT(sb + FULL_OFF + 8 * slot, (gc >> 2) & 1);

            const float* aP = sInF + slot * IN_STAGE + tig * IN_ROW + sbase + gid;
            // fragment-packed B: per k8, this lane's 8 floats are contiguous
            const float* bP = (const float*)(smem + EMB_OFF + slot * EMB_STAGE_B)
                              + (size_t)eg * 256 + lane * 8;
#pragma unroll
            for (int k8 = 0; k8 < 4; ++k8) {
                const int ka = k8 * 8 * IN_ROW;
                const float4 b0 = *(const float4*)(bP + k8 * 512);       // bf[0..3][0]
                const float4 b1 = *(const float4*)(bP + k8 * 512 + 4);   // bf[0..3][1]
                const uint32_t* u0 = (const uint32_t*)&b0;
                const uint32_t* u1 = (const uint32_t*)&b1;
#pragma unroll
                for (int i = 0; i < 2; ++i) {
                    uint32_t a0 = __float_as_uint(aP[ka + 16 * i]);
                    uint32_t a1 = __float_as_uint(aP[ka + 16 * i + 8]);
                    uint32_t a2 = __float_as_uint(aP[ka + 16 * i + 4 * IN_ROW]);
                    uint32_t a3 = __float_as_uint(aP[ka + 16 * i + 4 * IN_ROW + 8]);
#pragma unroll
                    for (int n = 0; n < 4; ++n)
                        mma_tf32(acc[i][n][0], acc[i][n][1], acc[i][n][2], acc[i][n][3],
                                 a0, a1, a2, a3, u0[n], u1[n]);
                }
            }
            __syncwarp();
            if (lane == 0) MBAR_ARRIVE(sb + EMPTY_OFF + 8 * slot);
        }

        // epilogue for this tile
        float* oB = out + ((size_t)(id >> 3) * Sdim + (id & 7) * S_TILE + sbase + gid) * Edim
                        + eg * 32 + tig * 2;
#pragma unroll
        for (int i = 0; i < 2; ++i) {
#pragma unroll
            for (int n = 0; n < 4; ++n) {
                float2 lo = make_float2(acc[i][n][0], acc[i][n][1]);
                float2 hi = make_float2(acc[i][n][2], acc[i][n][3]);
                *(float2*)(oB + (size_t)(16 * i) * Edim + 8 * n)     = lo;
                *(float2*)(oB + (size_t)(16 * i + 8) * Edim + 8 * n) = hi;
            }
        }
    }
}

extern "C" void kernel_launch(void* const* d_in, const int* in_sizes, int n_in,
                              void* d_out, int out_size) {
    const float* inp = (const float*)d_in[0];   // [128, 2048, 1024] fp32
    const float* emb = (const float*)d_in[1];   // [2048, 64] fp32
    float* out = (float*)d_out;                 // [128, 1024, 64] fp32

    pack_emb<<<(Vdim * Edim + 255) / 256, 256>>>(emb);

    cudaFuncSetAttribute(embed_mma_kernel,
                         cudaFuncAttributeMaxDynamicSharedMemorySize, SMEM_BYTES);
    embed_mma_kernel<<<NCTA, NTHR, SMEM_BYTES>>>(inp, out);
}

// round 14
// speedup vs baseline: 2.1111x; 1.1045x over previous
#include <cuda_runtime.h>
#include <cstdint>

#define Vdim 2048
#define Sdim 1024
#define Edim 64

#define NCONS  256                 // consumer threads (8 warps)
#define NPROD  128                 // producer threads (4 warps)
#define NTHR   (NCONS + NPROD)     // 384
#define KCH    32                  // v per chunk
#define NCHUNK (Vdim / KCH)        // 64
#define S_TILE 128
#define NSTG   4
#define NTILES ((Sdim / S_TILE) * 128)     // 1024
#define NCTA   304                 // 2 per SM x 152 SMs (GB300)

// smem layout: sIn rows padded 128->136 floats; emb fragment-packed (lane-major)
#define IN_ROW    136
#define IN_STAGE  (KCH * IN_ROW)           // 17408 B per stage
#define EMB_STAGE_B 8192                   // 2048 floats, fragment-packed
#define EMB_OFF   (NSTG * IN_STAGE * 4)    // 69632
#define STAGE_END (EMB_OFF + NSTG * EMB_STAGE_B)     // 102400
#define FULL_OFF   STAGE_END               // 4 x 8B
#define EMPTY_OFF  (STAGE_END + 32)
#define TFULL_OFF  (STAGE_END + 64)
#define TEMPTY_OFF (STAGE_END + 96)
#define TILEID_OFF (STAGE_END + 128)       // 4 x 4B
#define SMEM_BYTES (STAGE_END + 160)

// Fragment-packed emb, LANE-MAJOR (16B lane stride -> coalesced LDS.128):
//   chunk c (2048 floats) = 16 blocks of 128 floats (512B each)
//   block index = (k8*2 + eg)*2 + h,  h in {0(b0),1(b1)}
//   within block: lane*4 + j
//   value at p: v = c*32 + k8*8 + h*4 + tig,  e = eg*32 + gid + 8*j
//   (tig = lane&3, gid = lane>>2); tf32-RNA, pre-scaled by (1+2^-12)
__device__ __align__(16) float g_embP[Vdim * Edim];
__device__ int g_ticket;

__global__ void pack_emb(const float* __restrict__ emb) {
    int p = blockIdx.x * 256 + threadIdx.x;
    if (p == 0) g_ticket = 0;                 // reset scheduler every launch/replay
    if (p < Vdim * Edim) {
        int c    = p >> 11;
        int r    = p & 2047;
        int blk  = r >> 7;                    // 0..15
        int lane = (r >> 2) & 31;
        int j    = r & 3;
        int k8   = blk >> 2;
        int eg   = (blk >> 1) & 1;
        int h    = blk & 1;
        int tig  = lane & 3, gid = lane >> 2;
        int v = c * 32 + k8 * 8 + h * 4 + tig;
        int e = eg * 32 + gid + 8 * j;
        float val = emb[v * Edim + e] * 1.000244140625f;  // cancel input-trunc bias
        uint32_t rr;
        asm("cvt.rna.tf32.f32 %0, %1;" : "=r"(rr) : "f"(val));
        g_embP[p] = __uint_as_float(rr);
    }
}

__device__ __forceinline__ uint32_t smem_u32(const void* p) {
    uint32_t a;
    asm("{ .reg .u64 t; cvta.to.shared.u64 t, %1; cvt.u32.u64 %0, t; }" : "=r"(a) : "l"(p));
    return a;
}
__device__ __forceinline__ void cp16(uint32_t dst, const void* src) {
    asm volatile("cp.async.cg.shared.global [%0], [%1], 16;" :: "r"(dst), "l"(src) : "memory");
}
__device__ __forceinline__ void mma_tf32(float& c0, float& c1, float& c2, float& c3,
                                         uint32_t a0, uint32_t a1, uint32_t a2, uint32_t a3,
                                         uint32_t b0, uint32_t b1) {
    asm volatile(
        "mma.sync.aligned.m16n8k8.row.col.f32.tf32.tf32.f32 "
        "{%0,%1,%2,%3}, {%4,%5,%6,%7}, {%8,%9}, {%0,%1,%2,%3};"
        : "+f"(c0), "+f"(c1), "+f"(c2), "+f"(c3)
        : "r"(a0), "r"(a1), "r"(a2), "r"(a3), "r"(b0), "r"(b1));
}

#define MBAR_INIT(a, c) \
    asm volatile("mbarrier.init.shared.b64 [%0], %1;" :: "r"(a), "r"(c) : "memory")
#define MBAR_ARRIVE(a) \
    asm volatile("mbarrier.arrive.shared.b64 _, [%0];" :: "r"(a) : "memory")
#define CPASYNC_MBAR_ARRIVE(a) \
    asm volatile("cp.async.mbarrier.arrive.noinc.shared::cta.b64 [%0];" :: "r"(a) : "memory")
#define MBAR_WAIT(a, p) do {                                                      \
    uint32_t _done = 0;                                                           \
    while (!_done) {                                                              \
        asm volatile("{\n\t.reg .pred P;\n\t"                                     \
            "mbarrier.try_wait.parity.acquire.cta.shared::cta.b64 P, [%1], %2, 0x989680;\n\t" \
            "selp.b32 %0, 1, 0, P;\n\t}"                                          \
            : "=r"(_done) : "r"(a), "r"(p) : "memory");                           \
    } } while (0)

__global__ __launch_bounds__(NTHR, 2)
void embed_mma_kernel(const float* __restrict__ inp, float* __restrict__ out)
{
    extern __shared__ char smem[];
    float* sInF = (float*)smem;
    volatile int* tileIds = (volatile int*)(smem + TILEID_OFF);
    const uint32_t sb = smem_u32(smem);

    const int tid = threadIdx.x;

    if (tid == 0) {
#pragma unroll
        for (int s = 0; s < NSTG; ++s) {
            MBAR_INIT(sb + FULL_OFF   + 8 * s, NPROD);  // 128 noinc completion-arrives
            MBAR_INIT(sb + EMPTY_OFF  + 8 * s, 8);      // 8 consumer warp leaders
            MBAR_INIT(sb + TFULL_OFF  + 8 * s, 1);      // producer leader
            MBAR_INIT(sb + TEMPTY_OFF + 8 * s, 8);      // 8 consumer warp leaders
        }
    }
    __syncthreads();

    if (tid >= NCONS) {
        // ================= PRODUCER (4 warps) =================
        const int ptid = tid - NCONS;                   // 0..127
        int gc = 0;                                     // global chunk sequence
        for (int t = 0; ; ++t) {
            const int ts = t & 3;
            if (ptid == 0) {
                if (t >= 4) MBAR_WAIT(sb + TEMPTY_OFF + 8 * ts, ((t >> 2) - 1) & 1);
                int id = atomicAdd(&g_ticket, 1);
                if (id >= NTILES) id = -1;
                tileIds[ts] = id;
                MBAR_ARRIVE(sb + TFULL_OFF + 8 * ts);   // release: id visible to waiters
            }
            MBAR_WAIT(sb + TFULL_OFF + 8 * ts, (t >> 2) & 1);
            const int id = tileIds[ts];
            if (id < 0) break;
            const float* inB = inp + (size_t)(id >> 3) * Vdim * Sdim + (id & 7) * S_TILE;
            for (int c = 0; c < NCHUNK; ++c, ++gc) {
                const int slot = gc & 3;
                if (gc >= NSTG)
                    MBAR_WAIT(sb + EMPTY_OFF + 8 * slot, ((gc >> 2) - 1) & 1);
                const int v0 = c * KCH;
                uint32_t inDst  = sb + slot * (IN_STAGE * 4);
                uint32_t embDst = sb + EMB_OFF + slot * EMB_STAGE_B;
#pragma unroll
                for (int u = 0; u < 8; ++u) {           // input: 1024 float4 / 128 thr
                    int idx = ptid + u * NPROD;
                    int row = idx >> 5, col4 = idx & 31;
                    cp16(inDst + row * (IN_ROW * 4) + col4 * 16,
                         inB + (size_t)(v0 + row) * Sdim + col4 * 4);
                }
                // emb: 8192B contiguous (fragment-packed), 512 float4 / 128 thr
                const float* embSrc = g_embP + (size_t)c * 2048;
#pragma unroll
                for (int u = 0; u < 4; ++u) {
                    int idx = ptid + u * NPROD;
                    cp16(embDst + idx * 16, embSrc + idx * 4);
                }
                CPASYNC_MBAR_ARRIVE(sb + FULL_OFF + 8 * slot);
            }
        }
        return;
    }

    // ================= CONSUMER (8 warps, 32s x 32e warp tile) =================
    const int w    = tid >> 5;
    const int lane = tid & 31;
    const int sbase = (w & 3) * 32;
    const int eg    = w >> 2;            // e-half
    const int gid = lane >> 2, tig = lane & 3;

    int gc = 0;
    for (int t = 0; ; ++t) {
        const int ts = t & 3;
        MBAR_WAIT(sb + TFULL_OFF + 8 * ts, (t >> 2) & 1);
        const int id = tileIds[ts];
        __syncwarp();
        if (lane == 0) MBAR_ARRIVE(sb + TEMPTY_OFF + 8 * ts);
        if (id < 0) break;

        float acc[2][4][4];
#pragma unroll
        for (int i = 0; i < 2; ++i)
#pragma unroll
            for (int n = 0; n < 4; ++n)
#pragma unroll
                for (int cc = 0; cc < 4; ++cc) acc[i][n][cc] = 0.0f;

        for (int c = 0; c < NCHUNK; ++c, ++gc) {
            const int slot = gc & 3;
            MBAR_WAIT(sb + FULL_OFF + 8 * slot, (gc >> 2) & 1);

            const float* aP = sInF + slot * IN_STAGE + tig * IN_ROW + sbase + gid;
            // lane-major packed B: per (k8, eg): b0 block then b1 block, 512B each
            const char* bBase = smem + EMB_OFF + slot * EMB_STAGE_B
                                + eg * 1024 + lane * 16;
#pragma unroll
            for (int k8 = 0; k8 < 4; ++k8) {
                const int ka = k8 * 8 * IN_ROW;
                const float4 b0 = *(const float4*)(bBase + k8 * 2048);        // bf[0..3][0]
                const float4 b1 = *(const float4*)(bBase + k8 * 2048 + 512);  // bf[0..3][1]
                const uint32_t* u0 = (const uint32_t*)&b0;
                const uint32_t* u1 = (const uint32_t*)&b1;
#pragma unroll
                for (int i = 0; i < 2; ++i) {
                    uint32_t a0 = __float_as_uint(aP[ka + 16 * i]);
                    uint32_t a1 = __float_as_uint(aP[ka + 16 * i + 8]);
                    uint32_t a2 = __float_as_uint(aP[ka + 16 * i + 4 * IN_ROW]);
                    uint32_t a3 = __float_as_uint(aP[ka + 16 * i + 4 * IN_ROW + 8]);
#pragma unroll
                    for (int n = 0; n < 4; ++n)
                        mma_tf32(acc[i][n][0], acc[i][n][1], acc[i][n][2], acc[i][n][3],
                                 a0, a1, a2, a3, u0[n], u1[n]);
                }
            }
            __syncwarp();
            if (lane == 0) MBAR_ARRIVE(sb + EMPTY_OFF + 8 * slot);
        }

        // epilogue for this tile
        float* oB = out + ((size_t)(id >> 3) * Sdim + (id & 7) * S_TILE + sbase + gid) * Edim
                        + eg * 32 + tig * 2;
#pragma unroll
        for (int i = 0; i < 2; ++i) {
#pragma unroll
            for (int n = 0; n < 4; ++n) {
                float2 lo = make_float2(acc[i][n][0], acc[i][n][1]);
                float2 hi = make_float2(acc[i][n][2], acc[i][n][3]);
                *(float2*)(oB + (size_t)(16 * i) * Edim + 8 * n)     = lo;
                *(float2*)(oB + (size_t)(16 * i + 8) * Edim + 8 * n) = hi;
            }
        }
    }
}

extern "C" void kernel_launch(void* const* d_in, const int* in_sizes, int n_in,
                              void* d_out, int out_size) {
    const float* inp = (const float*)d_in[0];   // [128, 2048, 1024] fp32
    const float* emb = (const float*)d_in[1];   // [2048, 64] fp32
    float* out = (float*)d_out;                 // [128, 1024, 64] fp32

    pack_emb<<<(Vdim * Edim + 255) / 256, 256>>>(emb);

    cudaFuncSetAttribute(embed_mma_kernel,
                         cudaFuncAttributeMaxDynamicSharedMemorySize, SMEM_BYTES);
    embed_mma_kernel<<<NCTA, NTHR, SMEM_BYTES>>>(inp, out);
}

// round 15
// speedup vs baseline: 2.1366x; 1.0121x over previous
#include <cuda_runtime.h>
#include <cstdint>

#define Vdim 2048
#define Sdim 1024
#define Edim 64

#define NCONS  256                 // consumer threads (8 warps)
#define NPROD  128                 // producer threads (4 warps)
#define NTHR   (NCONS + NPROD)     // 384
#define KCH    32                  // v per chunk
#define NCHUNK (Vdim / KCH)        // 64
#define S_TILE 128
#define NSTG   4
#define NTILES ((Sdim / S_TILE) * 128)     // 1024
#define NCTA   304                 // 2 per SM x 152 SMs (GB300)

// smem layout (floats): sIn rows padded 128->136, sEmb rows 64->72
#define IN_ROW    136
#define IN_STAGE  (KCH * IN_ROW)           // 17408 B
#define EMB_ROW   72
#define EMB_STAGE (KCH * EMB_ROW)          // 9216 B
#define EMB_OFF   (NSTG * IN_STAGE * 4)    // 69632
#define STAGE_END (EMB_OFF + NSTG * EMB_STAGE * 4)   // 106496
#define FULL_OFF   STAGE_END               // 4 x 8B
#define EMPTY_OFF  (STAGE_END + 32)
#define TFULL_OFF  (STAGE_END + 64)
#define TEMPTY_OFF (STAGE_END + 96)
#define TILEID_OFF (STAGE_END + 128)       // 4 x 4B
#define SMEM_BYTES (STAGE_END + 160)

// emb, tf32-RNA-rounded, pre-scaled by (1+2^-12) to cancel input-truncation bias
__device__ __align__(16) float g_embR[Vdim * Edim];
__device__ int g_ticket;

__global__ void round_emb(const float* __restrict__ emb) {
    int i = blockIdx.x * 256 + threadIdx.x;
    if (i == 0) g_ticket = 0;                 // reset scheduler every launch/replay
    if (i < Vdim * Edim) {
        float v = emb[i] * 1.000244140625f;
        uint32_t r;
        asm("cvt.rna.tf32.f32 %0, %1;" : "=r"(r) : "f"(v));
        g_embR[i] = __uint_as_float(r);
    }
}

__device__ __forceinline__ uint32_t smem_u32(const void* p) {
    uint32_t a;
    asm("{ .reg .u64 t; cvta.to.shared.u64 t, %1; cvt.u32.u64 %0, t; }" : "=r"(a) : "l"(p));
    return a;
}
__device__ __forceinline__ void cp16(uint32_t dst, const void* src) {
    asm volatile("cp.async.cg.shared.global [%0], [%1], 16;" :: "r"(dst), "l"(src) : "memory");
}
__device__ __forceinline__ void mma_tf32(float& c0, float& c1, float& c2, float& c3,
                                         uint32_t a0, uint32_t a1, uint32_t a2, uint32_t a3,
                                         uint32_t b0, uint32_t b1) {
    asm volatile(
        "mma.sync.aligned.m16n8k8.row.col.f32.tf32.tf32.f32 "
        "{%0,%1,%2,%3}, {%4,%5,%6,%7}, {%8,%9}, {%0,%1,%2,%3};"
        : "+f"(c0), "+f"(c1), "+f"(c2), "+f"(c3)
        : "r"(a0), "r"(a1), "r"(a2), "r"(a3), "r"(b0), "r"(b1));
}

#define MBAR_INIT(a, c) \
    asm volatile("mbarrier.init.shared.b64 [%0], %1;" :: "r"(a), "r"(c) : "memory")
#define MBAR_ARRIVE(a) \
    asm volatile("mbarrier.arrive.shared.b64 _, [%0];" :: "r"(a) : "memory")
#define CPASYNC_MBAR_ARRIVE(a) \
    asm volatile("cp.async.mbarrier.arrive.noinc.shared::cta.b64 [%0];" :: "r"(a) : "memory")
#define MBAR_WAIT(a, p) do {                                                      \
    uint32_t _done = 0;                                                           \
    while (!_done) {                                                              \
        asm volatile("{\n\t.reg .pred P;\n\t"                                     \
            "mbarrier.try_wait.parity.acquire.cta.shared::cta.b64 P, [%1], %2, 0x989680;\n\t" \
            "selp.b32 %0, 1, 0, P;\n\t}"                                          \
            : "=r"(_done) : "r"(a), "r"(p) : "memory");                           \
    } } while (0)

__global__ __launch_bounds__(NTHR, 2)
void embed_mma_kernel(const float* __restrict__ inp, float* __restrict__ out)
{
    extern __shared__ char smem[];
    float* sInF  = (float*)smem;
    float* sEmbF = (float*)(smem + EMB_OFF);
    volatile int* tileIds = (volatile int*)(smem + TILEID_OFF);
    const uint32_t sb = smem_u32(smem);

    const int tid = threadIdx.x;

    if (tid == 0) {
#pragma unroll
        for (int s = 0; s < NSTG; ++s) {
            MBAR_INIT(sb + FULL_OFF   + 8 * s, NPROD);  // 128 noinc completion-arrives
            MBAR_INIT(sb + EMPTY_OFF  + 8 * s, 8);      // 8 consumer warp leaders
            MBAR_INIT(sb + TFULL_OFF  + 8 * s, 1);      // producer leader
            MBAR_INIT(sb + TEMPTY_OFF + 8 * s, 8);      // 8 consumer warp leaders
        }
    }
    __syncthreads();

    if (tid >= NCONS) {
        // ================= PRODUCER (4 warps) =================
        const int ptid = tid - NCONS;                   // 0..127
        int gc = 0;                                     // global chunk sequence
        for (int t = 0; ; ++t) {
            const int ts = t & 3;
            if (ptid == 0) {
                if (t >= 4) MBAR_WAIT(sb + TEMPTY_OFF + 8 * ts, ((t >> 2) - 1) & 1);
                int id = atomicAdd(&g_ticket, 1);
                if (id >= NTILES) id = -1;
                tileIds[ts] = id;
                MBAR_ARRIVE(sb + TFULL_OFF + 8 * ts);   // release: id visible to waiters
            }
            MBAR_WAIT(sb + TFULL_OFF + 8 * ts, (t >> 2) & 1);
            const int id = tileIds[ts];
            if (id < 0) break;
            const float* inB = inp + (size_t)(id >> 3) * Vdim * Sdim + (id & 7) * S_TILE;
            for (int c = 0; c < NCHUNK; ++c, ++gc) {
                const int slot = gc & 3;
                if (gc >= NSTG)
                    MBAR_WAIT(sb + EMPTY_OFF + 8 * slot, ((gc >> 2) - 1) & 1);
                const int v0 = c * KCH;
                uint32_t inDst  = sb + slot * (IN_STAGE * 4);
                uint32_t embDst = sb + EMB_OFF + slot * (EMB_STAGE * 4);
#pragma unroll
                for (int u = 0; u < 8; ++u) {           // input: 1024 float4 / 128 thr
                    int idx = ptid + u * NPROD;
                    int row = idx >> 5, col4 = idx & 31;
                    cp16(inDst + row * (IN_ROW * 4) + col4 * 16,
                         inB + (size_t)(v0 + row) * Sdim + col4 * 4);
                }
#pragma unroll
                for (int u = 0; u < 4; ++u) {           // emb: 512 float4 / 128 thr
                    int idx = ptid + u * NPROD;
                    int row = idx >> 4, col4 = idx & 15;
                    cp16(embDst + row * (EMB_ROW * 4) + col4 * 16,
                         g_embR + (size_t)(v0 + row) * Edim + col4 * 4);
                }
                CPASYNC_MBAR_ARRIVE(sb + FULL_OFF + 8 * slot);
            }
        }
        return;
    }

    // ================= CONSUMER (8 warps, 32s x 32e warp tile) =================
    const int w    = tid >> 5;
    const int lane = tid & 31;
    const int sbase = (w & 3) * 32;
    const int ebase = (w >> 2) * 32;
    const int gid = lane >> 2, tig = lane & 3;

    int gc = 0;
    for (int t = 0; ; ++t) {
        const int ts = t & 3;
        MBAR_WAIT(sb + TFULL_OFF + 8 * ts, (t >> 2) & 1);
        const int id = tileIds[ts];
        __syncwarp();
        if (lane == 0) MBAR_ARRIVE(sb + TEMPTY_OFF + 8 * ts);
        if (id < 0) break;

        float acc[2][4][4];
#pragma unroll
        for (int i = 0; i < 2; ++i)
#pragma unroll
            for (int n = 0; n < 4; ++n)
#pragma unroll
                for (int cc = 0; cc < 4; ++cc) acc[i][n][cc] = 0.0f;

        for (int c = 0; c < NCHUNK; ++c, ++gc) {
            const int slot = gc & 3;
            MBAR_WAIT(sb + FULL_OFF + 8 * slot, (gc >> 2) & 1);

            const float* aP = sInF  + slot * IN_STAGE  + tig * IN_ROW  + sbase + gid;
            const float* bP = sEmbF + slot * EMB_STAGE + tig * EMB_ROW + ebase + gid;
#pragma unroll
            for (int k8 = 0; k8 < 4; ++k8) {
                const int ka = k8 * 8 * IN_ROW;
                const int kb = k8 * 8 * EMB_ROW;
                uint32_t bf[4][2];
#pragma unroll
                for (int n = 0; n < 4; ++n) {
                    bf[n][0] = __float_as_uint(bP[kb + 8 * n]);
                    bf[n][1] = __float_as_uint(bP[kb + 4 * EMB_ROW + 8 * n]);
                }
#pragma unroll
                for (int i = 0; i < 2; ++i) {
                    uint32_t a0 = __float_as_uint(aP[ka + 16 * i]);
                    uint32_t a1 = __float_as_uint(aP[ka + 16 * i + 8]);
                    uint32_t a2 = __float_as_uint(aP[ka + 16 * i + 4 * IN_ROW]);
                    uint32_t a3 = __float_as_uint(aP[ka + 16 * i + 4 * IN_ROW + 8]);
#pragma unroll
                    for (int n = 0; n < 4; ++n)
                        mma_tf32(acc[i][n][0], acc[i][n][1], acc[i][n][2], acc[i][n][3],
                                 a0, a1, a2, a3, bf[n][0], bf[n][1]);
                }
            }
            __syncwarp();
            if (lane == 0) MBAR_ARRIVE(sb + EMPTY_OFF + 8 * slot);
        }

        // epilogue: streaming stores (L2-evict-first; output is never re-read)
        float* oB = out + ((size_t)(id >> 3) * Sdim + (id & 7) * S_TILE + sbase + gid) * Edim
                        + ebase + tig * 2;
#pragma unroll
        for (int i = 0; i < 2; ++i) {
#pragma unroll
            for (int n = 0; n < 4; ++n) {
                float2 lo = make_float2(acc[i][n][0], acc[i][n][1]);
                float2 hi = make_float2(acc[i][n][2], acc[i][n][3]);
                __stcs((float2*)(oB + (size_t)(16 * i) * Edim + 8 * n), lo);
                __stcs((float2*)(oB + (size_t)(16 * i + 8) * Edim + 8 * n), hi);
            }
        }
    }
}

extern "C" void kernel_launch(void* const* d_in, const int* in_sizes, int n_in,
                              void* d_out, int out_size) {
    const float* inp = (const float*)d_in[0];   // [128, 2048, 1024] fp32
    const float* emb = (const float*)d_in[1];   // [2048, 64] fp32
    float* out = (float*)d_out;                 // [128, 1024, 64] fp32

    round_emb<<<(Vdim * Edim + 255) / 256, 256>>>(emb);

    cudaFuncSetAttribute(embed_mma_kernel,
                         cudaFuncAttributeMaxDynamicSharedMemorySize, SMEM_BYTES);
    embed_mma_kernel<<<NCTA, NTHR, SMEM_BYTES>>>(inp, out);
}